// round 12
// baseline (speedup 1.0000x reference)
#include <cuda_runtime.h>
#include <cuda_bf16.h>
#include <math.h>

#define BB   4
#define SS   1024
#define DD   512
#define HH   8
#define DKK  64
#define KTOP 204
#define PDIM 64
#define NPAT 8

typedef unsigned long long ull;

// ---- scratch ----
__device__ float g_Qf[BB*SS*DD];
__device__ float g_Kf[BB*SS*DD];
__device__ float g_Vf[BB*SS*DD];
__device__ float g_Ctx[BB*SS*DD];
__device__ float g_S3[(size_t)BB*SS*SS];       // full-dim scores (flat 512-chain)
__device__ unsigned g_Mb[BB*SS*32];            // per-row bitmask (1024 bits)

// ---- packed f32x2 helpers ----
__device__ __forceinline__ ull ff2_fma(ull a, ull b, ull c) {
    ull d; asm("fma.rn.f32x2 %0, %1, %2, %3;" : "=l"(d) : "l"(a), "l"(b), "l"(c)); return d;
}
__device__ __forceinline__ float2 ff2_unpack(ull v) {
    float lo, hi; asm("mov.b64 {%0, %1}, %2;" : "=f"(lo), "=f"(hi) : "l"(v));
    return make_float2(lo, hi);
}

// ---- bf16 mma helpers ----
__device__ __forceinline__ void mma16816(float* c, const unsigned* a, const unsigned* b) {
    asm volatile("mma.sync.aligned.m16n8k16.row.col.f32.bf16.bf16.f32 "
        "{%0,%1,%2,%3}, {%4,%5,%6,%7}, {%8,%9}, {%0,%1,%2,%3};"
        : "+f"(c[0]), "+f"(c[1]), "+f"(c[2]), "+f"(c[3])
        : "r"(a[0]), "r"(a[1]), "r"(a[2]), "r"(a[3]), "r"(b[0]), "r"(b[1]));
}
__device__ __forceinline__ unsigned bfpack(__nv_bfloat16 a, __nv_bfloat16 b) {
    __nv_bfloat162 t = __halves2bfloat162(a, b);
    return *(unsigned*)&t;
}
__device__ __forceinline__ void bfsplit(float x, __nv_bfloat16& h, __nv_bfloat16& l) {
    h = __float2bfloat16(x);
    l = __float2bfloat16(x - __bfloat162float(h));
}

// ---------------- exact 64x64 GEMM: C = act(A @ W + bias) ----------------
// A panel stored pre-splatted ([a,a] pairs) so the FFMA2 splat operand is a raw
// LDS — zero pack MOVs. Operand values and per-output ascending-k chain order are
// bit-identical to all prior passing rounds (load-bearing for the mask path).
template<int ACT>
__global__ __launch_bounds__(256)
void gemm_bias_kernel(const float* __restrict__ A, const float* __restrict__ W,
                      const float* __restrict__ bias, float* __restrict__ C,
                      int M, int N, int K) {
    __shared__ __align__(16) float As2[16 * 132];  // [k][2*m] splatted
    __shared__ __align__(16) float Bs[16 * 68];    // [k][n]
    int tid = threadIdx.x;
    int tx = tid & 15, ty = tid >> 4;
    int m0 = blockIdx.y * 64, n0 = blockIdx.x * 64;
    ull acc2[4][2];
    #pragma unroll
    for (int i = 0; i < 4; i++) { acc2[i][0] = 0ull; acc2[i][1] = 0ull; }
    for (int k0 = 0; k0 < K; k0 += 16) {
        #pragma unroll
        for (int l = 0; l < 4; l++) {
            int idx = tid + l * 256;
            int r = idx >> 4, c = idx & 15;
            float a = A[(size_t)(m0 + r) * K + k0 + c];
            As2[c * 132 + 2 * r]     = a;
            As2[c * 132 + 2 * r + 1] = a;
        }
        #pragma unroll
        for (int l = 0; l < 4; l++) {
            int idx = tid + l * 256;
            int r = idx >> 6, c = idx & 63;
            Bs[r * 68 + c] = W[(size_t)(k0 + r) * N + n0 + c];
        }
        __syncthreads();
        #pragma unroll
        for (int kk = 0; kk < 16; kk++) {
            ulonglong2 aa01 = *(const ulonglong2*)&As2[kk * 132 + ty * 8];
            ulonglong2 aa23 = *(const ulonglong2*)&As2[kk * 132 + ty * 8 + 4];
            ulonglong2 bb   = *(const ulonglong2*)&Bs[kk * 68 + tx * 4];
            acc2[0][0] = ff2_fma(aa01.x, bb.x, acc2[0][0]);
            acc2[0][1] = ff2_fma(aa01.x, bb.y, acc2[0][1]);
            acc2[1][0] = ff2_fma(aa01.y, bb.x, acc2[1][0]);
            acc2[1][1] = ff2_fma(aa01.y, bb.y, acc2[1][1]);
            acc2[2][0] = ff2_fma(aa23.x, bb.x, acc2[2][0]);
            acc2[2][1] = ff2_fma(aa23.x, bb.y, acc2[2][1]);
            acc2[3][0] = ff2_fma(aa23.y, bb.x, acc2[3][0]);
            acc2[3][1] = ff2_fma(aa23.y, bb.y, acc2[3][1]);
        }
        __syncthreads();
    }
    #pragma unroll
    for (int i = 0; i < 4; i++) {
        int m = m0 + ty * 4 + i;
        #pragma unroll
        for (int jp = 0; jp < 2; jp++) {
            float2 v2 = ff2_unpack(acc2[i][jp]);
            int n = n0 + tx * 4 + jp * 2;
            float v = v2.x + bias[n];
            if (ACT == 1) v = fmaxf(v, 0.0f);
            if (ACT == 2) v = tanhf(v);
            C[(size_t)m * N + n] = v;
            v = v2.y + bias[n + 1];
            if (ACT == 1) v = fmaxf(v, 0.0f);
            if (ACT == 2) v = tanhf(v);
            C[(size_t)m * N + n + 1] = v;
        }
    }
}

// ---------------- merged QKV projection (bit-exact chains, load-bearing) ----------------
__global__ __launch_bounds__(256)
void qkv_kernel(const float* __restrict__ q, const float* __restrict__ k,
                const float* __restrict__ v,
                const float* __restrict__ wq, const float* __restrict__ bq,
                const float* __restrict__ wk, const float* __restrict__ bk,
                const float* __restrict__ wv, const float* __restrict__ bv,
                float* __restrict__ Qf, float* __restrict__ Kf, float* __restrict__ Vf) {
    __shared__ __align__(16) float As2[16 * 132];
    __shared__ __align__(16) float Bs[16 * 68];
    const float *A, *W, *bias; float* C;
    if (blockIdx.z == 0)      { A = q; W = wq; bias = bq; C = Qf; }
    else if (blockIdx.z == 1) { A = k; W = wk; bias = bk; C = Kf; }
    else                      { A = v; W = wv; bias = bv; C = Vf; }
    const int N = DD, K = DD;
    int tid = threadIdx.x;
    int tx = tid & 15, ty = tid >> 4;
    int m0 = blockIdx.y * 64, n0 = blockIdx.x * 64;
    ull acc2[4][2];
    #pragma unroll
    for (int i = 0; i < 4; i++) { acc2[i][0] = 0ull; acc2[i][1] = 0ull; }
    for (int k0 = 0; k0 < K; k0 += 16) {
        #pragma unroll
        for (int l = 0; l < 4; l++) {
            int idx = tid + l * 256;
            int r = idx >> 4, c = idx & 15;
            float a = A[(size_t)(m0 + r) * K + k0 + c];
            As2[c * 132 + 2 * r]     = a;
            As2[c * 132 + 2 * r + 1] = a;
        }
        #pragma unroll
        for (int l = 0; l < 4; l++) {
            int idx = tid + l * 256;
            int r = idx >> 6, c = idx & 63;
            Bs[r * 68 + c] = W[(size_t)(k0 + r) * N + n0 + c];
        }
        __syncthreads();
        #pragma unroll
        for (int kk = 0; kk < 16; kk++) {
            ulonglong2 aa01 = *(const ulonglong2*)&As2[kk * 132 + ty * 8];
            ulonglong2 aa23 = *(const ulonglong2*)&As2[kk * 132 + ty * 8 + 4];
            ulonglong2 bb   = *(const ulonglong2*)&Bs[kk * 68 + tx * 4];
            acc2[0][0] = ff2_fma(aa01.x, bb.x, acc2[0][0]);
            acc2[0][1] = ff2_fma(aa01.x, bb.y, acc2[0][1]);
            acc2[1][0] = ff2_fma(aa01.y, bb.x, acc2[1][0]);
            acc2[1][1] = ff2_fma(aa01.y, bb.y, acc2[1][1]);
            acc2[2][0] = ff2_fma(aa23.x, bb.x, acc2[2][0]);
            acc2[2][1] = ff2_fma(aa23.x, bb.y, acc2[2][1]);
            acc2[3][0] = ff2_fma(aa23.y, bb.x, acc2[3][0]);
            acc2[3][1] = ff2_fma(aa23.y, bb.y, acc2[3][1]);
        }
        __syncthreads();
    }
    #pragma unroll
    for (int i = 0; i < 4; i++) {
        int m = m0 + ty * 4 + i;
        #pragma unroll
        for (int jp = 0; jp < 2; jp++) {
            float2 v2 = ff2_unpack(acc2[i][jp]);
            int n = n0 + tx * 4 + jp * 2;
            C[(size_t)m * N + n]     = v2.x + bias[n];
            C[(size_t)m * N + n + 1] = v2.y + bias[n + 1];
        }
    }
}

// ------------- S3: 128x128 tile, pre-splat A, flat ascending-k (bit-exact) -------------
__global__ __launch_bounds__(256)
void s3_kernel(const float* __restrict__ Qf, const float* __restrict__ Kf,
               float* __restrict__ S3) {
    __shared__ __align__(16) float As2[16 * 260];  // [k][2*i] splatted
    __shared__ __align__(16) float Bs[16 * 132];   // [k][j]
    int b = blockIdx.z;
    int i0 = blockIdx.y * 128, j0 = blockIdx.x * 128;
    int tid = threadIdx.x, tx = tid & 15, ty = tid >> 4;
    const float* Qb = Qf + (size_t)b * SS * DD;
    const float* Kb = Kf + (size_t)b * SS * DD;
    ull acc[8][4];
    #pragma unroll
    for (int i = 0; i < 8; i++)
        #pragma unroll
        for (int j = 0; j < 4; j++) acc[i][j] = 0ull;
    for (int k0 = 0; k0 < DD; k0 += 16) {
        #pragma unroll
        for (int l = 0; l < 8; l++) {
            int idx = tid + l * 256;
            int r = idx >> 4, c = idx & 15;
            float a = Qb[(size_t)(i0 + r) * DD + k0 + c];
            As2[c * 260 + 2 * r]     = a;
            As2[c * 260 + 2 * r + 1] = a;
            Bs[c * 132 + r] = Kb[(size_t)(j0 + r) * DD + k0 + c];
        }
        __syncthreads();
        #pragma unroll
        for (int kk = 0; kk < 16; kk++) {
            ulonglong2 aa01 = *(const ulonglong2*)&As2[kk * 260 + ty * 16];
            ulonglong2 aa23 = *(const ulonglong2*)&As2[kk * 260 + ty * 16 + 4];
            ulonglong2 aa45 = *(const ulonglong2*)&As2[kk * 260 + ty * 16 + 8];
            ulonglong2 aa67 = *(const ulonglong2*)&As2[kk * 260 + ty * 16 + 12];
            ulonglong2 bb01 = *(const ulonglong2*)&Bs[kk * 132 + tx * 8];
            ulonglong2 bb23 = *(const ulonglong2*)&Bs[kk * 132 + tx * 8 + 4];
            ull aa[8] = {aa01.x, aa01.y, aa23.x, aa23.y, aa45.x, aa45.y, aa67.x, aa67.y};
            #pragma unroll
            for (int i = 0; i < 8; i++) {
                acc[i][0] = ff2_fma(aa[i], bb01.x, acc[i][0]);
                acc[i][1] = ff2_fma(aa[i], bb01.y, acc[i][1]);
                acc[i][2] = ff2_fma(aa[i], bb23.x, acc[i][2]);
                acc[i][3] = ff2_fma(aa[i], bb23.y, acc[i][3]);
            }
        }
        __syncthreads();
    }
    size_t b3 = ((size_t)b * SS + i0) * SS + j0;
    #pragma unroll
    for (int i = 0; i < 8; i++) {
        size_t ro = b3 + (size_t)(ty * 8 + i) * SS + tx * 8;
        #pragma unroll
        for (int jp = 0; jp < 4; jp++) {
            float2 v2 = ff2_unpack(acc[i][jp]);
            S3[ro + jp * 2]     = v2.x * 0.125f;
            S3[ro + jp * 2 + 1] = v2.y * 0.125f;
        }
    }
}

// ------------- row-wise top-204 (parallel suffix-scan selection) -------------
__global__ __launch_bounds__(256)
void topk_mask_kernel(const float* __restrict__ S3, float* __restrict__ maskOut,
                      unsigned* __restrict__ Mb) {
    __shared__ unsigned keys[1024];
    __shared__ int hist[256];
    __shared__ int ssum[256];
    __shared__ unsigned s_prefix;
    __shared__ int s_rem;
    int row = blockIdx.x;
    int b = row >> 10, i = row & 1023;
    int tid = threadIdx.x;
    const float* src = S3 + (size_t)row * SS;
    {
        float4 v = ((const float4*)src)[tid];
        float vv[4] = {v.x, v.y, v.z, v.w};
        #pragma unroll
        for (int e = 0; e < 4; e++) {
            unsigned bits = __float_as_uint(vv[e]);
            keys[tid * 4 + e] = (bits & 0x80000000u) ? ~bits : (bits | 0x80000000u);
        }
    }
    if (tid == 0) { s_prefix = 0u; s_rem = KTOP; }
    __syncthreads();
    for (int pass = 0; pass < 4; pass++) {
        int shift = 24 - pass * 8;
        hist[tid] = 0;
        __syncthreads();
        unsigned pref = s_prefix;
        int rem = s_rem;
        #pragma unroll
        for (int e = 0; e < 4; e++) {
            unsigned key = keys[tid * 4 + e];
            bool match = (pass == 0) || ((key >> (shift + 8)) == (pref >> (shift + 8)));
            if (match) atomicAdd(&hist[(key >> shift) & 255], 1);
        }
        __syncthreads();
        ssum[tid] = hist[tid];
        __syncthreads();
        #pragma unroll
        for (int off = 1; off < 256; off <<= 1) {
            int add = (tid + off < 256) ? ssum[tid + off] : 0;
            __syncthreads();
            ssum[tid] += add;
            __syncthreads();
        }
        int below = (tid == 255) ? 0 : ssum[tid + 1];
        if (ssum[tid] >= rem && below < rem) {
            s_prefix = pref | ((unsigned)tid << shift);
            s_rem = rem - below;
        }
        __syncthreads();
    }
    unsigned T = s_prefix;
    int need = s_rem;
    size_t maskBase = (size_t)b * HH * SS * SS + (size_t)i * SS;
    float m[4];
    unsigned nib = 0;
    #pragma unroll
    for (int e = 0; e < 4; e++) {
        int j = tid * 4 + e;
        unsigned key = keys[j];
        float mv = 0.0f;
        if (key > T) mv = 1.0f;
        else if (key == T) {
            int cnt = 0;
            for (int jj = 0; jj < j; jj++) cnt += (keys[jj] == T) ? 1 : 0;
            if (cnt < need) mv = 1.0f;
        }
        m[e] = mv;
        if (mv > 0.0f) nib |= 1u << e;
    }
    unsigned sh = nib << (4 * (tid & 7));
    sh |= __shfl_xor_sync(0xffffffffu, sh, 1);
    sh |= __shfl_xor_sync(0xffffffffu, sh, 2);
    sh |= __shfl_xor_sync(0xffffffffu, sh, 4);
    if ((tid & 7) == 0)
        Mb[(size_t)row * 32 + (tid >> 3)] = sh;
    float4 mvec = make_float4(m[0], m[1], m[2], m[3]);
    #pragma unroll
    for (int h = 0; h < HH; h++)
        *(float4*)&maskOut[maskBase + (size_t)h * SS * SS + tid * 4] = mvec;
}

// ------------- fused tensor-core attention (2 blocks/SM) -------------
#define BSTR 72
__global__ __launch_bounds__(256, 2)
void attn_tc_kernel(const float* __restrict__ Qf, const float* __restrict__ Kf,
                    const float* __restrict__ Vf, const unsigned* __restrict__ Mb,
                    float* __restrict__ Ctx) {
    extern __shared__ __nv_bfloat16 sb[];
    __nv_bfloat16* Qh = sb;
    __nv_bfloat16* Ql = sb + 128 * BSTR;
    __nv_bfloat16* Kh = sb + 256 * BSTR;
    __nv_bfloat16* Kl = sb + 320 * BSTR;
    __nv_bfloat16* Vh = sb + 384 * BSTR;
    __nv_bfloat16* Vl = sb + 448 * BSTR;
    int bh = blockIdx.y;
    int b = bh >> 3, h = bh & 7;
    int i0 = blockIdx.x * 128;
    int tid = threadIdx.x;
    int w = tid >> 5, lane = tid & 31;
    int g = lane >> 2, tig = lane & 3;

    for (int l = 0; l < 32; l++) {
        int idx = tid + l * 256;
        int r = idx >> 6, c = idx & 63;
        float qv = Qf[(size_t)(b * SS + i0 + r) * DD + h * 64 + c];
        __nv_bfloat16 hh, ll; bfsplit(qv, hh, ll);
        Qh[r * BSTR + c] = hh;
        Ql[r * BSTR + c] = ll;
    }
    __syncthreads();

    unsigned aQh[4][4], aQl[4][4];
    int rr = w * 16 + g;
    #pragma unroll
    for (int kc = 0; kc < 4; kc++) {
        aQh[kc][0] = *(const unsigned*)&Qh[rr * BSTR + kc * 16 + 2 * tig];
        aQh[kc][1] = *(const unsigned*)&Qh[(rr + 8) * BSTR + kc * 16 + 2 * tig];
        aQh[kc][2] = *(const unsigned*)&Qh[rr * BSTR + kc * 16 + 2 * tig + 8];
        aQh[kc][3] = *(const unsigned*)&Qh[(rr + 8) * BSTR + kc * 16 + 2 * tig + 8];
        aQl[kc][0] = *(const unsigned*)&Ql[rr * BSTR + kc * 16 + 2 * tig];
        aQl[kc][1] = *(const unsigned*)&Ql[(rr + 8) * BSTR + kc * 16 + 2 * tig];
        aQl[kc][2] = *(const unsigned*)&Ql[rr * BSTR + kc * 16 + 2 * tig + 8];
        aQl[kc][3] = *(const unsigned*)&Ql[(rr + 8) * BSTR + kc * 16 + 2 * tig + 8];
    }

    float oacc[8][4];
    #pragma unroll
    for (int dn = 0; dn < 8; dn++)
        #pragma unroll
        for (int r = 0; r < 4; r++) oacc[dn][r] = 0.0f;
    float rs0 = 0.0f, rs1 = 0.0f;
    int row0 = i0 + w * 16 + g, row1 = row0 + 8;
    const unsigned* mrow0 = Mb + (size_t)(b * SS + row0) * 32;
    const unsigned* mrow1 = Mb + (size_t)(b * SS + row1) * 32;

    for (int j0 = 0; j0 < SS; j0 += 64) {
        __syncthreads();
        for (int l = 0; l < 16; l++) {
            int idx = tid + l * 256;
            int r = idx >> 6, c = idx & 63;
            size_t go = (size_t)(b * SS + j0 + r) * DD + h * 64 + c;
            float kv = Kf[go];
            __nv_bfloat16 hh, ll; bfsplit(kv, hh, ll);
            Kh[r * BSTR + c] = hh;
            Kl[r * BSTR + c] = ll;
            float vv = Vf[go];
            bfsplit(vv, hh, ll);
            Vh[c * BSTR + r] = hh;
            Vl[c * BSTR + r] = ll;
        }
        __syncthreads();

        unsigned aPh[4][4], aPl[4][4];
        #pragma unroll
        for (int jn = 0; jn < 8; jn++) {
            float s[4] = {0.f, 0.f, 0.f, 0.f};
            #pragma unroll
            for (int kc = 0; kc < 4; kc++) {
                unsigned bh2[2], bl2[2];
                int krow = (jn * 8 + g) * BSTR + kc * 16 + 2 * tig;
                bh2[0] = *(const unsigned*)&Kh[krow];
                bh2[1] = *(const unsigned*)&Kh[krow + 8];
                bl2[0] = *(const unsigned*)&Kl[krow];
                bl2[1] = *(const unsigned*)&Kl[krow + 8];
                mma16816(s, aQh[kc], bh2);
                mma16816(s, aQl[kc], bh2);
                mma16816(s, aQh[kc], bl2);
            }
            int j = j0 + jn * 8 + 2 * tig;
            unsigned w0 = mrow0[j >> 5], w1 = mrow1[j >> 5];
            float p0 = ((w0 >> (j & 31)) & 1u) ? __expf(s[0] * 0.125f) : 0.0f;
            float p1 = ((w0 >> ((j + 1) & 31)) & 1u) ? __expf(s[1] * 0.125f) : 0.0f;
            float p2 = ((w1 >> (j & 31)) & 1u) ? __expf(s[2] * 0.125f) : 0.0f;
            float p3 = ((w1 >> ((j + 1) & 31)) & 1u) ? __expf(s[3] * 0.125f) : 0.0f;
            rs0 += p0 + p1;
            rs1 += p2 + p3;
            __nv_bfloat16 h0, l0, h1, l1, h2, l2, h3, l3;
            bfsplit(p0, h0, l0); bfsplit(p1, h1, l1);
            bfsplit(p2, h2, l2); bfsplit(p3, h3, l3);
            int kc = jn >> 1, half = (jn & 1) ? 2 : 0;
            aPh[kc][half + 0] = bfpack(h0, h1);
            aPh[kc][half + 1] = bfpack(h2, h3);
            aPl[kc][half + 0] = bfpack(l0, l1);
            aPl[kc][half + 1] = bfpack(l2, l3);
        }
        #pragma unroll
        for (int dn = 0; dn < 8; dn++) {
            #pragma unroll
            for (int kc = 0; kc < 4; kc++) {
                unsigned bvh[2], bvl[2];
                int vrow = (dn * 8 + g) * BSTR + kc * 16 + 2 * tig;
                bvh[0] = *(const unsigned*)&Vh[vrow];
                bvh[1] = *(const unsigned*)&Vh[vrow + 8];
                bvl[0] = *(const unsigned*)&Vl[vrow];
                bvl[1] = *(const unsigned*)&Vl[vrow + 8];
                mma16816(oacc[dn], aPh[kc], bvh);
                mma16816(oacc[dn], aPl[kc], bvh);
                mma16816(oacc[dn], aPh[kc], bvl);
            }
        }
    }
    rs0 += __shfl_xor_sync(0xffffffffu, rs0, 1);
    rs0 += __shfl_xor_sync(0xffffffffu, rs0, 2);
    rs1 += __shfl_xor_sync(0xffffffffu, rs1, 1);
    rs1 += __shfl_xor_sync(0xffffffffu, rs1, 2);
    float inv0 = 1.0f / rs0, inv1 = 1.0f / rs1;
    #pragma unroll
    for (int dn = 0; dn < 8; dn++) {
        int d = h * 64 + dn * 8 + 2 * tig;
        float2 v0 = make_float2(oacc[dn][0] * inv0, oacc[dn][1] * inv0);
        float2 v1 = make_float2(oacc[dn][2] * inv1, oacc[dn][3] * inv1);
        *(float2*)&Ctx[(size_t)(b * SS + row0) * DD + d] = v0;
        *(float2*)&Ctx[(size_t)(b * SS + row1) * DD + d] = v1;
    }
}

// ------------- fused pattern branch -------------
__global__ __launch_bounds__(256)
void pattern_fused_kernel(const float* __restrict__ q,
                          const float* __restrict__ pw1, const float* __restrict__ pb1,
                          const float* __restrict__ pw2, const float* __restrict__ pb2,
                          const float* __restrict__ bank, const float* __restrict__ gate,
                          float* __restrict__ outP) {
    __shared__ float As[16][33];
    __shared__ float Bs[16][65];
    __shared__ float H1[32][65];
    __shared__ float Enc[32][65];
    int tid = threadIdx.x, tx = tid & 15, ty = tid >> 4;
    int m0 = blockIdx.x * 32;
    float acc[2][4] = {};
    for (int k0 = 0; k0 < DD; k0 += 16) {
        #pragma unroll
        for (int l = 0; l < 2; l++) {
            int idx = tid + l * 256;
            int r = idx >> 4, c = idx & 15;
            As[c][r] = q[(size_t)(m0 + r) * DD + k0 + c];
        }
        #pragma unroll
        for (int l = 0; l < 4; l++) {
            int idx = tid + l * 256;
            int r = idx >> 6, c = idx & 63;
            Bs[r][c] = pw1[(size_t)(k0 + r) * PDIM + c];
        }
        __syncthreads();
        #pragma unroll
        for (int kk = 0; kk < 16; kk++) {
            float a0 = As[kk][ty * 2], a1 = As[kk][ty * 2 + 1];
            #pragma unroll
            for (int j = 0; j < 4; j++) {
                float bb = Bs[kk][tx * 4 + j];
                acc[0][j] = fmaf(a0, bb, acc[0][j]);
                acc[1][j] = fmaf(a1, bb, acc[1][j]);
            }
        }
        __syncthreads();
    }
    #pragma unroll
    for (int i = 0; i < 2; i++)
        #pragma unroll
        for (int j = 0; j < 4; j++)
            H1[ty * 2 + i][tx * 4 + j] = fmaxf(acc[i][j] + pb1[tx * 4 + j], 0.0f);
    __syncthreads();
    float acc2[2][4] = {};
    for (int k0 = 0; k0 < PDIM; k0 += 16) {
        #pragma unroll
        for (int l = 0; l < 4; l++) {
            int idx = tid + l * 256;
            int r = idx >> 6, c = idx & 63;
            Bs[idx >> 6][c] = pw2[(size_t)(k0 + r) * PDIM + c];
        }
        __syncthreads();
        #pragma unroll
        for (int kk = 0; kk < 16; kk++) {
            float a0 = H1[ty * 2][k0 + kk], a1 = H1[ty * 2 + 1][k0 + kk];
            #pragma unroll
            for (int j = 0; j < 4; j++) {
                float bb = Bs[kk][tx * 4 + j];
                acc2[0][j] = fmaf(a0, bb, acc2[0][j]);
                acc2[1][j] = fmaf(a1, bb, acc2[1][j]);
            }
        }
        __syncthreads();
    }
    #pragma unroll
    for (int i = 0; i < 2; i++)
        #pragma unroll
        for (int j = 0; j < 4; j++)
            Enc[ty * 2 + i][tx * 4 + j] = tanhf(acc2[i][j] + pb2[tx * 4 + j]);
    __syncthreads();
    int row = tid >> 3, p = tid & 7;
    float d = 0.0f;
    #pragma unroll
    for (int k = 0; k < PDIM; k++)
        d = fmaf(Enc[row][k], bank[p * PDIM + k], d);
    float s = d * 0.125f;
    float mx = s;
    #pragma unroll
    for (int o = 1; o < 8; o <<= 1) mx = fmaxf(mx, __shfl_xor_sync(0xffffffffu, mx, o));
    float e = expf(s - mx);
    float sum = e;
    #pragma unroll
    for (int o = 1; o < 8; o <<= 1) sum += __shfl_xor_sync(0xffffffffu, sum, o);
    outP[(size_t)(m0 + row) * NPAT + p] = e / sum * gate[p];
}

extern "C" void kernel_launch(void* const* d_in, const int* in_sizes, int n_in,
                              void* d_out, int out_size) {
    const float* query = (const float*)d_in[0];
    const float* key   = (const float*)d_in[1];
    const float* value = (const float*)d_in[2];
    const float* wq = (const float*)d_in[3];  const float* bq = (const float*)d_in[4];
    const float* wk = (const float*)d_in[5];  const float* bk = (const float*)d_in[6];
    const float* wv = (const float*)d_in[7];  const float* bv = (const float*)d_in[8];
    const float* wo = (const float*)d_in[9];  const float* bo = (const float*)d_in[10];
    const float* pw1 = (const float*)d_in[11]; const float* pb1 = (const float*)d_in[12];
    const float* pw2 = (const float*)d_in[13]; const float* pb2 = (const float*)d_in[14];
    const float* bank = (const float*)d_in[15];
    const float* gate = (const float*)d_in[16];
    float* out = (float*)d_out;

    void *pQf, *pKf, *pVf, *pCtx, *pS3, *pMb;
    cudaGetSymbolAddress(&pQf, g_Qf);
    cudaGetSymbolAddress(&pKf, g_Kf);
    cudaGetSymbolAddress(&pVf, g_Vf);
    cudaGetSymbolAddress(&pCtx, g_Ctx);
    cudaGetSymbolAddress(&pS3, g_S3);
    cudaGetSymbolAddress(&pMb, g_Mb);
    float* Qf = (float*)pQf;   float* Kf = (float*)pKf;
    float* Vf = (float*)pVf;   float* Ctx = (float*)pCtx;
    float* S3 = (float*)pS3;   unsigned* Mb = (unsigned*)pMb;

    const size_t maskOff  = (size_t)BB * SS * DD;
    const size_t patOff   = maskOff + (size_t)BB * HH * SS * SS;
    float* outAttn = out;
    float* outMask = out + maskOff;
    float* outPat  = out + patOff;

    const int M = BB * SS;   // 4096
    dim3 blk(256);

    const int ATTN_SMEM = 512 * BSTR * sizeof(__nv_bfloat16);  // 73728 B
    cudaFuncSetAttribute(attn_tc_kernel,
                         cudaFuncAttributeMaxDynamicSharedMemorySize, ATTN_SMEM);

    // QKV projections (one launch, bit-exact chains — load-bearing for mask)
    qkv_kernel<<<dim3(DD / 64, M / 64, 3), blk>>>(query, key, value,
                                                  wq, bq, wk, bk, wv, bv,
                                                  Qf, Kf, Vf);

    // fused pattern branch
    pattern_fused_kernel<<<dim3(M / 32), blk>>>(query, pw1, pb1, pw2, pb2,
                                                bank, gate, outPat);

    // flat-chain full-dim scores (exact, 128x128 tile, pre-splat A)
    s3_kernel<<<dim3(SS / 128, SS / 128, BB), blk>>>(Qf, Kf, S3);

    // top-204: parallel-scan selection, float4 mask writes + bitmask
    topk_mask_kernel<<<dim3(BB * SS), blk>>>(S3, outMask, Mb);

    // fused tensor-core attention (bf16x3 QK + exp + bf16x3 PV)
    attn_tc_kernel<<<dim3(SS / 128, BB * HH), blk, ATTN_SMEM>>>(Qf, Kf, Vf, Mb, Ctx);

    // output projection (exact 64x64, pre-splat A)
    gemm_bias_kernel<0><<<dim3(DD / 64, M / 64), blk>>>(Ctx, wo, bo, outAttn, M, DD, DD);
}

// round 15
// speedup vs baseline: 1.2383x; 1.2383x over previous
#include <cuda_runtime.h>
#include <cuda_bf16.h>
#include <math.h>

#define BB   4
#define SS   1024
#define DD   512
#define HH   8
#define DKK  64
#define KTOP 204
#define PDIM 64
#define NPAT 8

typedef unsigned long long ull;

// ---- scratch ----
__device__ float g_Qf[BB*SS*DD];
__device__ float g_Kf[BB*SS*DD];
__device__ float g_Vf[BB*SS*DD];
__device__ float g_Ctx[BB*SS*DD];
__device__ float g_S3[(size_t)BB*SS*SS];       // full-dim scores (flat 512-chain)
__device__ unsigned g_Mb[BB*SS*32];            // per-row bitmask (1024 bits)

// ---- packed f32x2 helpers ----
__device__ __forceinline__ ull ff2_pack(float lo, float hi) {
    ull r; asm("mov.b64 %0, {%1, %2};" : "=l"(r) : "f"(lo), "f"(hi)); return r;
}
__device__ __forceinline__ ull ff2_fma(ull a, ull b, ull c) {
    ull d; asm("fma.rn.f32x2 %0, %1, %2, %3;" : "=l"(d) : "l"(a), "l"(b), "l"(c)); return d;
}
__device__ __forceinline__ float2 ff2_unpack(ull v) {
    float lo, hi; asm("mov.b64 {%0, %1}, %2;" : "=f"(lo), "=f"(hi) : "l"(v));
    return make_float2(lo, hi);
}

// ---- bf16 mma helpers ----
__device__ __forceinline__ void mma16816(float* c, const unsigned* a, const unsigned* b) {
    asm volatile("mma.sync.aligned.m16n8k16.row.col.f32.bf16.bf16.f32 "
        "{%0,%1,%2,%3}, {%4,%5,%6,%7}, {%8,%9}, {%0,%1,%2,%3};"
        : "+f"(c[0]), "+f"(c[1]), "+f"(c[2]), "+f"(c[3])
        : "r"(a[0]), "r"(a[1]), "r"(a[2]), "r"(a[3]), "r"(b[0]), "r"(b[1]));
}
__device__ __forceinline__ unsigned bfpack(__nv_bfloat16 a, __nv_bfloat16 b) {
    __nv_bfloat162 t = __halves2bfloat162(a, b);
    return *(unsigned*)&t;
}
__device__ __forceinline__ void bfsplit(float x, __nv_bfloat16& h, __nv_bfloat16& l) {
    h = __float2bfloat16(x);
    l = __float2bfloat16(x - __bfloat162float(h));
}

// ---- double-buffered exact GEMM body (chain order identical to R11) ----
// Computes 64x64 tile of C = A@W; inner loop is the proven ff2_pack FFMA2 chain.
__device__ __forceinline__ void gemm64_db_body(const float* __restrict__ A,
                                               const float* __restrict__ W,
                                               float (&As)[2][16][68],
                                               float (&Bs)[2][16][68],
                                               ull (&acc2)[4][2],
                                               int m0, int n0, int N, int K) {
    int tid = threadIdx.x;
    int tx = tid & 15, ty = tid >> 4;
    // preload panel 0 into buffer 0
    #pragma unroll
    for (int l = 0; l < 4; l++) {
        int idx = tid + l * 256;
        int r = idx >> 4, c = idx & 15;
        As[0][c][r] = A[(size_t)(m0 + r) * K + c];
    }
    #pragma unroll
    for (int l = 0; l < 4; l++) {
        int idx = tid + l * 256;
        int r = idx >> 6, c = idx & 63;
        Bs[0][r][c] = W[(size_t)r * N + n0 + c];
    }
    __syncthreads();
    int buf = 0;
    for (int k0 = 0; k0 < K; k0 += 16) {
        int nxt = buf ^ 1;
        if (k0 + 16 < K) {
            #pragma unroll
            for (int l = 0; l < 4; l++) {
                int idx = tid + l * 256;
                int r = idx >> 4, c = idx & 15;
                As[nxt][c][r] = A[(size_t)(m0 + r) * K + k0 + 16 + c];
            }
            #pragma unroll
            for (int l = 0; l < 4; l++) {
                int idx = tid + l * 256;
                int r = idx >> 6, c = idx & 63;
                Bs[nxt][r][c] = W[(size_t)(k0 + 16 + r) * N + n0 + c];
            }
        }
        #pragma unroll
        for (int kk = 0; kk < 16; kk++) {
            float4 a4 = *(const float4*)&As[buf][kk][ty * 4];
            float4 b4 = *(const float4*)&Bs[buf][kk][tx * 4];
            ull b01 = ff2_pack(b4.x, b4.y);
            ull b23 = ff2_pack(b4.z, b4.w);
            ull aa;
            aa = ff2_pack(a4.x, a4.x);
            acc2[0][0] = ff2_fma(aa, b01, acc2[0][0]);
            acc2[0][1] = ff2_fma(aa, b23, acc2[0][1]);
            aa = ff2_pack(a4.y, a4.y);
            acc2[1][0] = ff2_fma(aa, b01, acc2[1][0]);
            acc2[1][1] = ff2_fma(aa, b23, acc2[1][1]);
            aa = ff2_pack(a4.z, a4.z);
            acc2[2][0] = ff2_fma(aa, b01, acc2[2][0]);
            acc2[2][1] = ff2_fma(aa, b23, acc2[2][1]);
            aa = ff2_pack(a4.w, a4.w);
            acc2[3][0] = ff2_fma(aa, b01, acc2[3][0]);
            acc2[3][1] = ff2_fma(aa, b23, acc2[3][1]);
        }
        __syncthreads();
        buf = nxt;
    }
}

// ---------------- generic GEMM: C = act(A @ W + bias) (exact, double-buffered) ----------------
template<int ACT>
__global__ __launch_bounds__(256)
void gemm_bias_kernel(const float* __restrict__ A, const float* __restrict__ W,
                      const float* __restrict__ bias, float* __restrict__ C,
                      int M, int N, int K) {
    __shared__ __align__(16) float As[2][16][68];
    __shared__ __align__(16) float Bs[2][16][68];
    int tid = threadIdx.x;
    int tx = tid & 15, ty = tid >> 4;
    int m0 = blockIdx.y * 64, n0 = blockIdx.x * 64;
    ull acc2[4][2];
    #pragma unroll
    for (int i = 0; i < 4; i++) { acc2[i][0] = 0ull; acc2[i][1] = 0ull; }
    gemm64_db_body(A, W, As, Bs, acc2, m0, n0, N, K);
    #pragma unroll
    for (int i = 0; i < 4; i++) {
        int m = m0 + ty * 4 + i;
        #pragma unroll
        for (int jp = 0; jp < 2; jp++) {
            float2 v2 = ff2_unpack(acc2[i][jp]);
            int n = n0 + tx * 4 + jp * 2;
            float v = v2.x + bias[n];
            if (ACT == 1) v = fmaxf(v, 0.0f);
            if (ACT == 2) v = tanhf(v);
            C[(size_t)m * N + n] = v;
            v = v2.y + bias[n + 1];
            if (ACT == 1) v = fmaxf(v, 0.0f);
            if (ACT == 2) v = tanhf(v);
            C[(size_t)m * N + n + 1] = v;
        }
    }
}

// ---------------- merged QKV projection (bit-exact chains, double-buffered) ----------------
__global__ __launch_bounds__(256)
void qkv_kernel(const float* __restrict__ q, const float* __restrict__ k,
                const float* __restrict__ v,
                const float* __restrict__ wq, const float* __restrict__ bq,
                const float* __restrict__ wk, const float* __restrict__ bk,
                const float* __restrict__ wv, const float* __restrict__ bv,
                float* __restrict__ Qf, float* __restrict__ Kf, float* __restrict__ Vf) {
    __shared__ __align__(16) float As[2][16][68];
    __shared__ __align__(16) float Bs[2][16][68];
    const float *A, *W, *bias; float* C;
    if (blockIdx.z == 0)      { A = q; W = wq; bias = bq; C = Qf; }
    else if (blockIdx.z == 1) { A = k; W = wk; bias = bk; C = Kf; }
    else                      { A = v; W = wv; bias = bv; C = Vf; }
    int tid = threadIdx.x;
    int tx = tid & 15, ty = tid >> 4;
    int m0 = blockIdx.y * 64, n0 = blockIdx.x * 64;
    ull acc2[4][2];
    #pragma unroll
    for (int i = 0; i < 4; i++) { acc2[i][0] = 0ull; acc2[i][1] = 0ull; }
    gemm64_db_body(A, W, As, Bs, acc2, m0, n0, DD, DD);
    #pragma unroll
    for (int i = 0; i < 4; i++) {
        int m = m0 + ty * 4 + i;
        #pragma unroll
        for (int jp = 0; jp < 2; jp++) {
            float2 v2 = ff2_unpack(acc2[i][jp]);
            int n = n0 + tx * 4 + jp * 2;
            C[(size_t)m * DD + n]     = v2.x + bias[n];
            C[(size_t)m * DD + n + 1] = v2.y + bias[n + 1];
        }
    }
}

// ------------- S3: 128x128 tile, flat ascending-k (bit-exact, load-bearing) -------------
__global__ __launch_bounds__(256)
void s3_kernel(const float* __restrict__ Qf, const float* __restrict__ Kf,
               float* __restrict__ S3) {
    __shared__ __align__(16) float As[16][132];
    __shared__ __align__(16) float Bs[16][132];
    int b = blockIdx.z;
    int i0 = blockIdx.y * 128, j0 = blockIdx.x * 128;
    int tid = threadIdx.x, tx = tid & 15, ty = tid >> 4;
    const float* Qb = Qf + (size_t)b * SS * DD;
    const float* Kb = Kf + (size_t)b * SS * DD;
    ull acc[8][4];
    #pragma unroll
    for (int i = 0; i < 8; i++)
        #pragma unroll
        for (int j = 0; j < 4; j++) acc[i][j] = 0ull;
    for (int k0 = 0; k0 < DD; k0 += 16) {
        #pragma unroll
        for (int l = 0; l < 8; l++) {
            int idx = tid + l * 256;
            int r = idx >> 4, c = idx & 15;
            As[c][r] = Qb[(size_t)(i0 + r) * DD + k0 + c];
            Bs[c][r] = Kb[(size_t)(j0 + r) * DD + k0 + c];
        }
        __syncthreads();
        #pragma unroll
        for (int kk = 0; kk < 16; kk++) {
            float4 a0 = *(const float4*)&As[kk][ty * 8];
            float4 a1 = *(const float4*)&As[kk][ty * 8 + 4];
            float4 b0 = *(const float4*)&Bs[kk][tx * 8];
            float4 b1 = *(const float4*)&Bs[kk][tx * 8 + 4];
            ull bp[4];
            bp[0] = ff2_pack(b0.x, b0.y);
            bp[1] = ff2_pack(b0.z, b0.w);
            bp[2] = ff2_pack(b1.x, b1.y);
            bp[3] = ff2_pack(b1.z, b1.w);
            float av[8] = {a0.x, a0.y, a0.z, a0.w, a1.x, a1.y, a1.z, a1.w};
            #pragma unroll
            for (int i = 0; i < 8; i++) {
                ull aa = ff2_pack(av[i], av[i]);
                acc[i][0] = ff2_fma(aa, bp[0], acc[i][0]);
                acc[i][1] = ff2_fma(aa, bp[1], acc[i][1]);
                acc[i][2] = ff2_fma(aa, bp[2], acc[i][2]);
                acc[i][3] = ff2_fma(aa, bp[3], acc[i][3]);
            }
        }
        __syncthreads();
    }
    size_t b3 = ((size_t)b * SS + i0) * SS + j0;
    #pragma unroll
    for (int i = 0; i < 8; i++) {
        size_t ro = b3 + (size_t)(ty * 8 + i) * SS + tx * 8;
        #pragma unroll
        for (int jp = 0; jp < 4; jp++) {
            float2 v2 = ff2_unpack(acc[i][jp]);
            S3[ro + jp * 2]     = v2.x * 0.125f;
            S3[ro + jp * 2 + 1] = v2.y * 0.125f;
        }
    }
}

// ------------- row-wise top-204 (parallel suffix-scan selection) -------------
__global__ __launch_bounds__(256)
void topk_mask_kernel(const float* __restrict__ S3, float* __restrict__ maskOut,
                      unsigned* __restrict__ Mb) {
    __shared__ unsigned keys[1024];
    __shared__ int hist[256];
    __shared__ int ssum[256];
    __shared__ unsigned s_prefix;
    __shared__ int s_rem;
    int row = blockIdx.x;
    int b = row >> 10, i = row & 1023;
    int tid = threadIdx.x;
    const float* src = S3 + (size_t)row * SS;
    {
        float4 v = ((const float4*)src)[tid];
        float vv[4] = {v.x, v.y, v.z, v.w};
        #pragma unroll
        for (int e = 0; e < 4; e++) {
            unsigned bits = __float_as_uint(vv[e]);
            keys[tid * 4 + e] = (bits & 0x80000000u) ? ~bits : (bits | 0x80000000u);
        }
    }
    if (tid == 0) { s_prefix = 0u; s_rem = KTOP; }
    __syncthreads();
    for (int pass = 0; pass < 4; pass++) {
        int shift = 24 - pass * 8;
        hist[tid] = 0;
        __syncthreads();
        unsigned pref = s_prefix;
        int rem = s_rem;
        #pragma unroll
        for (int e = 0; e < 4; e++) {
            unsigned key = keys[tid * 4 + e];
            bool match = (pass == 0) || ((key >> (shift + 8)) == (pref >> (shift + 8)));
            if (match) atomicAdd(&hist[(key >> shift) & 255], 1);
        }
        __syncthreads();
        ssum[tid] = hist[tid];
        __syncthreads();
        #pragma unroll
        for (int off = 1; off < 256; off <<= 1) {
            int add = (tid + off < 256) ? ssum[tid + off] : 0;
            __syncthreads();
            ssum[tid] += add;
            __syncthreads();
        }
        int below = (tid == 255) ? 0 : ssum[tid + 1];
        if (ssum[tid] >= rem && below < rem) {
            s_prefix = pref | ((unsigned)tid << shift);
            s_rem = rem - below;
        }
        __syncthreads();
    }
    unsigned T = s_prefix;
    int need = s_rem;
    size_t maskBase = (size_t)b * HH * SS * SS + (size_t)i * SS;
    float m[4];
    unsigned nib = 0;
    #pragma unroll
    for (int e = 0; e < 4; e++) {
        int j = tid * 4 + e;
        unsigned key = keys[j];
        float mv = 0.0f;
        if (key > T) mv = 1.0f;
        else if (key == T) {
            int cnt = 0;
            for (int jj = 0; jj < j; jj++) cnt += (keys[jj] == T) ? 1 : 0;
            if (cnt < need) mv = 1.0f;
        }
        m[e] = mv;
        if (mv > 0.0f) nib |= 1u << e;
    }
    unsigned sh = nib << (4 * (tid & 7));
    sh |= __shfl_xor_sync(0xffffffffu, sh, 1);
    sh |= __shfl_xor_sync(0xffffffffu, sh, 2);
    sh |= __shfl_xor_sync(0xffffffffu, sh, 4);
    if ((tid & 7) == 0)
        Mb[(size_t)row * 32 + (tid >> 3)] = sh;
    float4 mvec = make_float4(m[0], m[1], m[2], m[3]);
    #pragma unroll
    for (int h = 0; h < HH; h++)
        *(float4*)&maskOut[maskBase + (size_t)h * SS * SS + tid * 4] = mvec;
}

// ------------- fused tensor-core attention (2 blocks/SM) -------------
#define BSTR 72
__global__ __launch_bounds__(256, 2)
void attn_tc_kernel(const float* __restrict__ Qf, const float* __restrict__ Kf,
                    const float* __restrict__ Vf, const unsigned* __restrict__ Mb,
                    float* __restrict__ Ctx) {
    extern __shared__ __nv_bfloat16 sb[];
    __nv_bfloat16* Qh = sb;
    __nv_bfloat16* Ql = sb + 128 * BSTR;
    __nv_bfloat16* Kh = sb + 256 * BSTR;
    __nv_bfloat16* Kl = sb + 320 * BSTR;
    __nv_bfloat16* Vh = sb + 384 * BSTR;
    __nv_bfloat16* Vl = sb + 448 * BSTR;
    int bh = blockIdx.y;
    int b = bh >> 3, h = bh & 7;
    int i0 = blockIdx.x * 128;
    int tid = threadIdx.x;
    int w = tid >> 5, lane = tid & 31;
    int g = lane >> 2, tig = lane & 3;

    for (int l = 0; l < 32; l++) {
        int idx = tid + l * 256;
        int r = idx >> 6, c = idx & 63;
        float qv = Qf[(size_t)(b * SS + i0 + r) * DD + h * 64 + c];
        __nv_bfloat16 hh, ll; bfsplit(qv, hh, ll);
        Qh[r * BSTR + c] = hh;
        Ql[r * BSTR + c] = ll;
    }
    __syncthreads();

    unsigned aQh[4][4], aQl[4][4];
    int rr = w * 16 + g;
    #pragma unroll
    for (int kc = 0; kc < 4; kc++) {
        aQh[kc][0] = *(const unsigned*)&Qh[rr * BSTR + kc * 16 + 2 * tig];
        aQh[kc][1] = *(const unsigned*)&Qh[(rr + 8) * BSTR + kc * 16 + 2 * tig];
        aQh[kc][2] = *(const unsigned*)&Qh[rr * BSTR + kc * 16 + 2 * tig + 8];
        aQh[kc][3] = *(const unsigned*)&Qh[(rr + 8) * BSTR + kc * 16 + 2 * tig + 8];
        aQl[kc][0] = *(const unsigned*)&Ql[rr * BSTR + kc * 16 + 2 * tig];
        aQl[kc][1] = *(const unsigned*)&Ql[(rr + 8) * BSTR + kc * 16 + 2 * tig];
        aQl[kc][2] = *(const unsigned*)&Ql[rr * BSTR + kc * 16 + 2 * tig + 8];
        aQl[kc][3] = *(const unsigned*)&Ql[(rr + 8) * BSTR + kc * 16 + 2 * tig + 8];
    }

    float oacc[8][4];
    #pragma unroll
    for (int dn = 0; dn < 8; dn++)
        #pragma unroll
        for (int r = 0; r < 4; r++) oacc[dn][r] = 0.0f;
    float rs0 = 0.0f, rs1 = 0.0f;
    int row0 = i0 + w * 16 + g, row1 = row0 + 8;
    const unsigned* mrow0 = Mb + (size_t)(b * SS + row0) * 32;
    const unsigned* mrow1 = Mb + (size_t)(b * SS + row1) * 32;

    for (int j0 = 0; j0 < SS; j0 += 64) {
        __syncthreads();
        for (int l = 0; l < 16; l++) {
            int idx = tid + l * 256;
            int r = idx >> 6, c = idx & 63;
            size_t go = (size_t)(b * SS + j0 + r) * DD + h * 64 + c;
            float kv = Kf[go];
            __nv_bfloat16 hh, ll; bfsplit(kv, hh, ll);
            Kh[r * BSTR + c] = hh;
            Kl[r * BSTR + c] = ll;
            float vv = Vf[go];
            bfsplit(vv, hh, ll);
            Vh[c * BSTR + r] = hh;
            Vl[c * BSTR + r] = ll;
        }
        __syncthreads();

        unsigned aPh[4][4], aPl[4][4];
        #pragma unroll
        for (int jn = 0; jn < 8; jn++) {
            float s[4] = {0.f, 0.f, 0.f, 0.f};
            #pragma unroll
            for (int kc = 0; kc < 4; kc++) {
                unsigned bh2[2], bl2[2];
                int krow = (jn * 8 + g) * BSTR + kc * 16 + 2 * tig;
                bh2[0] = *(const unsigned*)&Kh[krow];
                bh2[1] = *(const unsigned*)&Kh[krow + 8];
                bl2[0] = *(const unsigned*)&Kl[krow];
                bl2[1] = *(const unsigned*)&Kl[krow + 8];
                mma16816(s, aQh[kc], bh2);
                mma16816(s, aQl[kc], bh2);
                mma16816(s, aQh[kc], bl2);
            }
            int j = j0 + jn * 8 + 2 * tig;
            unsigned w0 = mrow0[j >> 5], w1 = mrow1[j >> 5];
            float p0 = ((w0 >> (j & 31)) & 1u) ? __expf(s[0] * 0.125f) : 0.0f;
            float p1 = ((w0 >> ((j + 1) & 31)) & 1u) ? __expf(s[1] * 0.125f) : 0.0f;
            float p2 = ((w1 >> (j & 31)) & 1u) ? __expf(s[2] * 0.125f) : 0.0f;
            float p3 = ((w1 >> ((j + 1) & 31)) & 1u) ? __expf(s[3] * 0.125f) : 0.0f;
            rs0 += p0 + p1;
            rs1 += p2 + p3;
            __nv_bfloat16 h0, l0, h1, l1, h2, l2, h3, l3;
            bfsplit(p0, h0, l0); bfsplit(p1, h1, l1);
            bfsplit(p2, h2, l2); bfsplit(p3, h3, l3);
            int kc = jn >> 1, half = (jn & 1) ? 2 : 0;
            aPh[kc][half + 0] = bfpack(h0, h1);
            aPh[kc][half + 1] = bfpack(h2, h3);
            aPl[kc][half + 0] = bfpack(l0, l1);
            aPl[kc][half + 1] = bfpack(l2, l3);
        }
        #pragma unroll
        for (int dn = 0; dn < 8; dn++) {
            #pragma unroll
            for (int kc = 0; kc < 4; kc++) {
                unsigned bvh[2], bvl[2];
                int vrow = (dn * 8 + g) * BSTR + kc * 16 + 2 * tig;
                bvh[0] = *(const unsigned*)&Vh[vrow];
                bvh[1] = *(const unsigned*)&Vh[vrow + 8];
                bvl[0] = *(const unsigned*)&Vl[vrow];
                bvl[1] = *(const unsigned*)&Vl[vrow + 8];
                mma16816(oacc[dn], aPh[kc], bvh);
                mma16816(oacc[dn], aPl[kc], bvh);
                mma16816(oacc[dn], aPh[kc], bvl);
            }
        }
    }
    rs0 += __shfl_xor_sync(0xffffffffu, rs0, 1);
    rs0 += __shfl_xor_sync(0xffffffffu, rs0, 2);
    rs1 += __shfl_xor_sync(0xffffffffu, rs1, 1);
    rs1 += __shfl_xor_sync(0xffffffffu, rs1, 2);
    float inv0 = 1.0f / rs0, inv1 = 1.0f / rs1;
    #pragma unroll
    for (int dn = 0; dn < 8; dn++) {
        int d = h * 64 + dn * 8 + 2 * tig;
        float2 v0 = make_float2(oacc[dn][0] * inv0, oacc[dn][1] * inv0);
        float2 v1 = make_float2(oacc[dn][2] * inv1, oacc[dn][3] * inv1);
        *(float2*)&Ctx[(size_t)(b * SS + row0) * DD + d] = v0;
        *(float2*)&Ctx[(size_t)(b * SS + row1) * DD + d] = v1;
    }
}

// ------------- fused pattern branch -------------
__global__ __launch_bounds__(256)
void pattern_fused_kernel(const float* __restrict__ q,
                          const float* __restrict__ pw1, const float* __restrict__ pb1,
                          const float* __restrict__ pw2, const float* __restrict__ pb2,
                          const float* __restrict__ bank, const float* __restrict__ gate,
                          float* __restrict__ outP) {
    __shared__ float As[16][33];
    __shared__ float Bs[16][65];
    __shared__ float H1[32][65];
    __shared__ float Enc[32][65];
    int tid = threadIdx.x, tx = tid & 15, ty = tid >> 4;
    int m0 = blockIdx.x * 32;
    float acc[2][4] = {};
    for (int k0 = 0; k0 < DD; k0 += 16) {
        #pragma unroll
        for (int l = 0; l < 2; l++) {
            int idx = tid + l * 256;
            int r = idx >> 4, c = idx & 15;
            As[c][r] = q[(size_t)(m0 + r) * DD + k0 + c];
        }
        #pragma unroll
        for (int l = 0; l < 4; l++) {
            int idx = tid + l * 256;
            int r = idx >> 6, c = idx & 63;
            Bs[r][c] = pw1[(size_t)(k0 + r) * PDIM + c];
        }
        __syncthreads();
        #pragma unroll
        for (int kk = 0; kk < 16; kk++) {
            float a0 = As[kk][ty * 2], a1 = As[kk][ty * 2 + 1];
            #pragma unroll
            for (int j = 0; j < 4; j++) {
                float bb = Bs[kk][tx * 4 + j];
                acc[0][j] = fmaf(a0, bb, acc[0][j]);
                acc[1][j] = fmaf(a1, bb, acc[1][j]);
            }
        }
        __syncthreads();
    }
    #pragma unroll
    for (int i = 0; i < 2; i++)
        #pragma unroll
        for (int j = 0; j < 4; j++)
            H1[ty * 2 + i][tx * 4 + j] = fmaxf(acc[i][j] + pb1[tx * 4 + j], 0.0f);
    __syncthreads();
    float acc2[2][4] = {};
    for (int k0 = 0; k0 < PDIM; k0 += 16) {
        #pragma unroll
        for (int l = 0; l < 4; l++) {
            int idx = tid + l * 256;
            int r = idx >> 6, c = idx & 63;
            Bs[idx >> 6][c] = pw2[(size_t)(k0 + r) * PDIM + c];
        }
        __syncthreads();
        #pragma unroll
        for (int kk = 0; kk < 16; kk++) {
            float a0 = H1[ty * 2][k0 + kk], a1 = H1[ty * 2 + 1][k0 + kk];
            #pragma unroll
            for (int j = 0; j < 4; j++) {
                float bb = Bs[kk][tx * 4 + j];
                acc2[0][j] = fmaf(a0, bb, acc2[0][j]);
                acc2[1][j] = fmaf(a1, bb, acc2[1][j]);
            }
        }
        __syncthreads();
    }
    #pragma unroll
    for (int i = 0; i < 2; i++)
        #pragma unroll
        for (int j = 0; j < 4; j++)
            Enc[ty * 2 + i][tx * 4 + j] = tanhf(acc2[i][j] + pb2[tx * 4 + j]);
    __syncthreads();
    int row = tid >> 3, p = tid & 7;
    float d = 0.0f;
    #pragma unroll
    for (int k = 0; k < PDIM; k++)
        d = fmaf(Enc[row][k], bank[p * PDIM + k], d);
    float s = d * 0.125f;
    float mx = s;
    #pragma unroll
    for (int o = 1; o < 8; o <<= 1) mx = fmaxf(mx, __shfl_xor_sync(0xffffffffu, mx, o));
    float e = expf(s - mx);
    float sum = e;
    #pragma unroll
    for (int o = 1; o < 8; o <<= 1) sum += __shfl_xor_sync(0xffffffffu, sum, o);
    outP[(size_t)(m0 + row) * NPAT + p] = e / sum * gate[p];
}

extern "C" void kernel_launch(void* const* d_in, const int* in_sizes, int n_in,
                              void* d_out, int out_size) {
    const float* query = (const float*)d_in[0];
    const float* key   = (const float*)d_in[1];
    const float* value = (const float*)d_in[2];
    const float* wq = (const float*)d_in[3];  const float* bq = (const float*)d_in[4];
    const float* wk = (const float*)d_in[5];  const float* bk = (const float*)d_in[6];
    const float* wv = (const float*)d_in[7];  const float* bv = (const float*)d_in[8];
    const float* wo = (const float*)d_in[9];  const float* bo = (const float*)d_in[10];
    const float* pw1 = (const float*)d_in[11]; const float* pb1 = (const float*)d_in[12];
    const float* pw2 = (const float*)d_in[13]; const float* pb2 = (const float*)d_in[14];
    const float* bank = (const float*)d_in[15];
    const float* gate = (const float*)d_in[16];
    float* out = (float*)d_out;

    void *pQf, *pKf, *pVf, *pCtx, *pS3, *pMb;
    cudaGetSymbolAddress(&pQf, g_Qf);
    cudaGetSymbolAddress(&pKf, g_Kf);
    cudaGetSymbolAddress(&pVf, g_Vf);
    cudaGetSymbolAddress(&pCtx, g_Ctx);
    cudaGetSymbolAddress(&pS3, g_S3);
    cudaGetSymbolAddress(&pMb, g_Mb);
    float* Qf = (float*)pQf;   float* Kf = (float*)pKf;
    float* Vf = (float*)pVf;   float* Ctx = (float*)pCtx;
    float* S3 = (float*)pS3;   unsigned* Mb = (unsigned*)pMb;

    const size_t maskOff  = (size_t)BB * SS * DD;
    const size_t patOff   = maskOff + (size_t)BB * HH * SS * SS;
    float* outAttn = out;
    float* outMask = out + maskOff;
    float* outPat  = out + patOff;

    const int M = BB * SS;   // 4096
    dim3 blk(256);

    const int ATTN_SMEM = 512 * BSTR * sizeof(__nv_bfloat16);  // 73728 B
    cudaFuncSetAttribute(attn_tc_kernel,
                         cudaFuncAttributeMaxDynamicSharedMemorySize, ATTN_SMEM);

    // QKV projections (one launch, bit-exact chains — load-bearing for mask)
    qkv_kernel<<<dim3(DD / 64, M / 64, 3), blk>>>(query, key, value,
                                                  wq, bq, wk, bk, wv, bv,
                                                  Qf, Kf, Vf);

    // fused pattern branch
    pattern_fused_kernel<<<dim3(M / 32), blk>>>(query, pw1, pb1, pw2, pb2,
                                                bank, gate, outPat);

    // flat-chain full-dim scores (exact, 128x128 tile)
    s3_kernel<<<dim3(SS / 128, SS / 128, BB), blk>>>(Qf, Kf, S3);

    // top-204: parallel-scan selection, float4 mask writes + bitmask
    topk_mask_kernel<<<dim3(BB * SS), blk>>>(S3, outMask, Mb);

    // fused tensor-core attention (bf16x3 QK + exp + bf16x3 PV)
    attn_tc_kernel<<<dim3(SS / 128, BB * HH), blk, ATTN_SMEM>>>(Qf, Kf, Vf, Mb, Ctx);

    // output projection (exact, double-buffered)
    gemm_bias_kernel<0><<<dim3(DD / 64, M / 64), blk>>>(Ctx, wo, bo, outAttn, M, DD, DD);
}